// round 1
// baseline (speedup 1.0000x reference)
#include <cuda_runtime.h>
#include <math.h>

#define HEADS 12
#define SEQ   2048
#define DIM   64
#define EMB   768
#define BATCH 4
#define MROWS (BATCH*SEQ)   // 8192

// Scratch (static device globals — no allocation)
__device__ float g_Q[BATCH*HEADS*SEQ*DIM];   // [B,H,S,D]
__device__ float g_K[BATCH*HEADS*SEQ*DIM];
__device__ float g_V[BATCH*HEADS*SEQ*DIM];
__device__ float g_AO[MROWS*EMB];            // attention out, [B*S, 768]

// ---------------------------------------------------------------------------
// NT GEMM: C[m][n] = sum_k A[m][k] * W[n][k] + bias[n]
// A: [M, 768] row-major, W: [N, 768] row-major.
// Block tile 128x64, thread tile 8x4, K-tile 16, 256 threads.
// LAYOUT 0: dst[((b*HEADS + h)*SEQ + s)*DIM + d] = val*scale   (h = blockIdx.y)
// LAYOUT 1: dst[m*EMB + n] = beta*val + alpha*add[m*EMB + n]
// ---------------------------------------------------------------------------
template<int LAYOUT>
__global__ void __launch_bounds__(256)
gemm_nt(const float* __restrict__ A, const float* __restrict__ W,
        const float* __restrict__ bias, float* __restrict__ dst,
        float scale,
        const float* __restrict__ alphaP, const float* __restrict__ betaP,
        const float* __restrict__ add)
{
    __shared__ float As[16][132];   // [k][m], pad 4 (16B-aligned rows, spread banks)
    __shared__ float Bs[16][68];    // [k][n]

    const int tid = threadIdx.x;
    const int tx = tid & 15;        // col group (4 cols)
    const int ty = tid >> 4;        // row group (8 rows)
    const int m0 = blockIdx.x * 128;
    const int n0 = blockIdx.y * 64;

    float acc[8][4];
#pragma unroll
    for (int i = 0; i < 8; i++)
#pragma unroll
        for (int j = 0; j < 4; j++) acc[i][j] = 0.f;

    for (int k0 = 0; k0 < EMB; k0 += 16) {
        // A tile: 128x16 = 512 float4, 2 per thread
#pragma unroll
        for (int u = 0; u < 2; u++) {
            int idx = tid + u * 256;
            int m   = idx >> 2;
            int kc  = (idx & 3) * 4;
            float4 v = *(const float4*)&A[(size_t)(m0 + m) * EMB + k0 + kc];
            As[kc + 0][m] = v.x; As[kc + 1][m] = v.y;
            As[kc + 2][m] = v.z; As[kc + 3][m] = v.w;
        }
        // W tile: 64x16 = 256 float4, 1 per thread
        {
            int n  = tid >> 2;
            int kc = (tid & 3) * 4;
            float4 v = *(const float4*)&W[(size_t)(n0 + n) * EMB + k0 + kc];
            Bs[kc + 0][n] = v.x; Bs[kc + 1][n] = v.y;
            Bs[kc + 2][n] = v.z; Bs[kc + 3][n] = v.w;
        }
        __syncthreads();

#pragma unroll
        for (int k = 0; k < 16; k++) {
            float a[8], b[4];
            float4 t0 = *(float4*)&As[k][ty * 8];
            float4 t1 = *(float4*)&As[k][ty * 8 + 4];
            a[0] = t0.x; a[1] = t0.y; a[2] = t0.z; a[3] = t0.w;
            a[4] = t1.x; a[5] = t1.y; a[6] = t1.z; a[7] = t1.w;
            float4 tb = *(float4*)&Bs[k][tx * 4];
            b[0] = tb.x; b[1] = tb.y; b[2] = tb.z; b[3] = tb.w;
#pragma unroll
            for (int i = 0; i < 8; i++)
#pragma unroll
                for (int j = 0; j < 4; j++)
                    acc[i][j] += a[i] * b[j];
        }
        __syncthreads();
    }

    if (LAYOUT == 0) {
        const int h = blockIdx.y;               // BN == DIM, tile == one head
#pragma unroll
        for (int i = 0; i < 8; i++) {
            int m = m0 + ty * 8 + i;
            int b = m >> 11;                    // /2048
            int s = m & 2047;
            int d = tx * 4;
            size_t base = (((size_t)(b * HEADS + h)) * SEQ + s) * DIM + d;
            float4 o;
            o.x = (acc[i][0] + bias[n0 + d + 0]) * scale;
            o.y = (acc[i][1] + bias[n0 + d + 1]) * scale;
            o.z = (acc[i][2] + bias[n0 + d + 2]) * scale;
            o.w = (acc[i][3] + bias[n0 + d + 3]) * scale;
            *(float4*)&dst[base] = o;
        }
    } else {
        const float al = *alphaP;
        const float be = *betaP;
#pragma unroll
        for (int i = 0; i < 8; i++) {
            int m = m0 + ty * 8 + i;
            size_t r = (size_t)m * EMB + n0 + tx * 4;
            float4 ad = *(const float4*)&add[r];
            float4 o;
            o.x = be * (acc[i][0] + bias[n0 + tx * 4 + 0]) + al * ad.x;
            o.y = be * (acc[i][1] + bias[n0 + tx * 4 + 1]) + al * ad.y;
            o.z = be * (acc[i][2] + bias[n0 + tx * 4 + 2]) + al * ad.z;
            o.w = be * (acc[i][3] + bias[n0 + tx * 4 + 3]) + al * ad.w;
            *(float4*)&dst[r] = o;
        }
    }
}

// ---------------------------------------------------------------------------
// Flash attention: block = (64 queries) x one (b,h); KV tiles of 32.
// 8 warps, each warp owns 8 query rows. Lane owns 1 kv col (score phase)
// and 2 d cols (accumulate phase). Online softmax.
// Q already pre-scaled by 1/sqrt(768).
// ---------------------------------------------------------------------------
__device__ __forceinline__ float warpMax(float v) {
#pragma unroll
    for (int o = 16; o > 0; o >>= 1)
        v = fmaxf(v, __shfl_xor_sync(0xffffffffu, v, o));
    return v;
}
__device__ __forceinline__ float warpSum(float v) {
#pragma unroll
    for (int o = 16; o > 0; o >>= 1)
        v += __shfl_xor_sync(0xffffffffu, v, o);
    return v;
}

__global__ void __launch_bounds__(256) attn_kernel()
{
    __shared__ float Ks[32][68];       // pad 4: conflict-free LDS.128 per-lane rows
    __shared__ float Vs[32][64];
    __shared__ float Qs[64][64];
    __shared__ float Ps[8][8][32];     // [warp][row][kv]

    const int tid  = threadIdx.x;
    const int lane = tid & 31;
    const int w    = tid >> 5;
    const int bh   = blockIdx.y;
    const int q0   = blockIdx.x * 64;

    const float* Qb = g_Q + ((size_t)bh * SEQ + q0) * DIM;
    const float* Kb = g_K + (size_t)bh * SEQ * DIM;
    const float* Vb = g_V + (size_t)bh * SEQ * DIM;

    // Load Q tile: 64x64 = 1024 float4, 4 per thread
#pragma unroll
    for (int u = 0; u < 4; u++) {
        int idx = tid + u * 256;
        int row = idx >> 4;
        int c   = (idx & 15) * 4;
        *(float4*)&Qs[row][c] = *(const float4*)&Qb[row * DIM + c];
    }

    float mr[8], lr[8], acc[8][2];
#pragma unroll
    for (int r = 0; r < 8; r++) {
        mr[r] = -1e30f; lr[r] = 0.f;
        acc[r][0] = 0.f; acc[r][1] = 0.f;
    }
    __syncthreads();

    for (int t = 0; t < SEQ / 32; t++) {
        const float* Kt = Kb + (size_t)t * 32 * DIM;
        const float* Vt = Vb + (size_t)t * 32 * DIM;
        // K tile: 32x64 = 512 float4, 2 per thread; same for V
#pragma unroll
        for (int u = 0; u < 2; u++) {
            int idx = tid + u * 256;
            int row = idx >> 4;
            int c   = (idx & 15) * 4;
            *(float4*)&Ks[row][c] = *(const float4*)&Kt[row * DIM + c];
        }
#pragma unroll
        for (int u = 0; u < 2; u++) {
            int idx = tid + u * 256;
            int row = idx >> 4;
            int c   = (idx & 15) * 4;
            *(float4*)&Vs[row][c] = *(const float4*)&Vt[row * DIM + c];
        }
        __syncthreads();

        // Scores: s[r] = dot(Q[w*8+r], K[lane])
        float s[8];
#pragma unroll
        for (int r = 0; r < 8; r++) s[r] = 0.f;
#pragma unroll
        for (int kk = 0; kk < DIM; kk += 4) {
            float4 kv = *(float4*)&Ks[lane][kk];
#pragma unroll
            for (int r = 0; r < 8; r++) {
                float4 qv = *(float4*)&Qs[w * 8 + r][kk];
                s[r] += qv.x * kv.x + qv.y * kv.y + qv.z * kv.z + qv.w * kv.w;
            }
        }

        // Online softmax
#pragma unroll
        for (int r = 0; r < 8; r++) {
            float tmax = warpMax(s[r]);
            float nm   = fmaxf(mr[r], tmax);
            float corr = __expf(mr[r] - nm);
            float p    = __expf(s[r] - nm);
            float ps   = warpSum(p);
            lr[r] = lr[r] * corr + ps;
            mr[r] = nm;
            acc[r][0] *= corr;
            acc[r][1] *= corr;
            Ps[w][r][lane] = p;
        }
        __syncwarp();

        // Accumulate: acc[r][d] += sum_j P[r][j] * V[j][d], d = 2*lane, 2*lane+1
#pragma unroll
        for (int jb = 0; jb < 32; jb += 4) {
            float2 v0 = *(float2*)&Vs[jb + 0][lane * 2];
            float2 v1 = *(float2*)&Vs[jb + 1][lane * 2];
            float2 v2 = *(float2*)&Vs[jb + 2][lane * 2];
            float2 v3 = *(float2*)&Vs[jb + 3][lane * 2];
#pragma unroll
            for (int r = 0; r < 8; r++) {
                float4 pv = *(float4*)&Ps[w][r][jb];
                acc[r][0] += pv.x * v0.x + pv.y * v1.x + pv.z * v2.x + pv.w * v3.x;
                acc[r][1] += pv.x * v0.y + pv.y * v1.y + pv.z * v2.y + pv.w * v3.y;
            }
        }
        __syncthreads();
    }

    // Write [B, S, 768]
    const int b = bh / HEADS;
    const int h = bh % HEADS;
#pragma unroll
    for (int r = 0; r < 8; r++) {
        int q = q0 + w * 8 + r;
        float inv = 1.f / lr[r];
        float2 o;
        o.x = acc[r][0] * inv;
        o.y = acc[r][1] * inv;
        *(float2*)&g_AO[((size_t)(b * SEQ + q)) * EMB + h * DIM + lane * 2] = o;
    }
}

// ---------------------------------------------------------------------------
extern "C" void kernel_launch(void* const* d_in, const int* in_sizes, int n_in,
                              void* d_out, int out_size)
{
    const float* v1    = (const float*)d_in[0];
    const float* v2    = (const float*)d_in[1];
    const float* Wq    = (const float*)d_in[2];
    const float* bq    = (const float*)d_in[3];
    const float* Wk    = (const float*)d_in[4];
    const float* bk    = (const float*)d_in[5];
    const float* Wv    = (const float*)d_in[6];
    const float* bv    = (const float*)d_in[7];
    const float* Wo    = (const float*)d_in[8];
    const float* bo    = (const float*)d_in[9];
    const float* alpha = (const float*)d_in[10];
    const float* beta  = (const float*)d_in[11];
    float* out = (float*)d_out;

    float *Qp, *Kp, *Vp, *AOp;
    cudaGetSymbolAddress((void**)&Qp,  g_Q);
    cudaGetSymbolAddress((void**)&Kp,  g_K);
    cudaGetSymbolAddress((void**)&Vp,  g_V);
    cudaGetSymbolAddress((void**)&AOp, g_AO);

    const float qscale = 1.0f / sqrtf((float)EMB);   // scores use Q/sqrt(768)
    dim3 gg(MROWS / 128, EMB / 64);

    gemm_nt<0><<<gg, 256>>>(v1, Wq, bq, Qp, qscale, nullptr, nullptr, nullptr);
    gemm_nt<0><<<gg, 256>>>(v2, Wk, bk, Kp, 1.0f,  nullptr, nullptr, nullptr);
    gemm_nt<0><<<gg, 256>>>(v2, Wv, bv, Vp, 1.0f,  nullptr, nullptr, nullptr);

    attn_kernel<<<dim3(SEQ / 64, BATCH * HEADS), 256>>>();

    gemm_nt<1><<<gg, 256>>>(v1, Wo, bo, out, 1.0f, alpha, beta, AOp);
}

// round 5
// speedup vs baseline: 2.7401x; 2.7401x over previous
#include <cuda_runtime.h>
#include <cuda_bf16.h>
#include <math.h>
#include <stdint.h>

#define HEADS 12
#define SEQ   2048
#define DIM   64
#define EMB   768
#define BATCH 4
#define MROWS (BATCH*SEQ)   // 8192

// ---------------- scratch (static device globals; no allocation) ----------
__device__ float g_AO[MROWS*EMB];            // attention out, [B*S, 768]

__device__ __nv_bfloat16 g_Qh[BATCH*HEADS*SEQ*DIM];
__device__ __nv_bfloat16 g_Ql[BATCH*HEADS*SEQ*DIM];
__device__ __nv_bfloat16 g_Kh[BATCH*HEADS*SEQ*DIM];
__device__ __nv_bfloat16 g_Kl[BATCH*HEADS*SEQ*DIM];
__device__ __nv_bfloat16 g_Vh[BATCH*HEADS*SEQ*DIM];
__device__ __nv_bfloat16 g_Vl[BATCH*HEADS*SEQ*DIM];

__device__ __nv_bfloat16 g_v1h[MROWS*EMB];
__device__ __nv_bfloat16 g_v1l[MROWS*EMB];
__device__ __nv_bfloat16 g_v2h[MROWS*EMB];
__device__ __nv_bfloat16 g_v2l[MROWS*EMB];
__device__ __nv_bfloat16 g_Wh[4*EMB*EMB];    // slots: 0=q 1=k 2=v 3=o
__device__ __nv_bfloat16 g_Wl[4*EMB*EMB];

// ---------------- helpers --------------------------------------------------
__device__ __forceinline__ uint32_t smem_u32(const void* p) {
    uint32_t a;
    asm("{ .reg .u64 t; cvta.to.shared.u64 t, %1; cvt.u32.u64 %0, t; }"
        : "=r"(a) : "l"(p));
    return a;
}
__device__ __forceinline__ void mma16816(float* c, const uint32_t* a,
                                         uint32_t b0, uint32_t b1) {
    asm volatile(
        "mma.sync.aligned.m16n8k16.row.col.f32.bf16.bf16.f32 "
        "{%0,%1,%2,%3}, {%4,%5,%6,%7}, {%8,%9}, {%0,%1,%2,%3};"
        : "+f"(c[0]), "+f"(c[1]), "+f"(c[2]), "+f"(c[3])
        : "r"(a[0]), "r"(a[1]), "r"(a[2]), "r"(a[3]), "r"(b0), "r"(b1));
}
__device__ __forceinline__ void ldm_x4(uint32_t* r, uint32_t addr) {
    asm volatile("ldmatrix.sync.aligned.m8n8.x4.shared.b16 {%0,%1,%2,%3}, [%4];"
                 : "=r"(r[0]), "=r"(r[1]), "=r"(r[2]), "=r"(r[3]) : "r"(addr));
}
__device__ __forceinline__ void ldm_x2(uint32_t* r, uint32_t addr) {
    asm volatile("ldmatrix.sync.aligned.m8n8.x2.shared.b16 {%0,%1}, [%2];"
                 : "=r"(r[0]), "=r"(r[1]) : "r"(addr));
}
__device__ __forceinline__ void ldm_x2t(uint32_t* r, uint32_t addr) {
    asm volatile("ldmatrix.sync.aligned.m8n8.x2.trans.shared.b16 {%0,%1}, [%2];"
                 : "=r"(r[0]), "=r"(r[1]) : "r"(addr));
}
__device__ __forceinline__ uint32_t packbf(float lo, float hi) {
    __nv_bfloat162 t = __floats2bfloat162_rn(lo, hi);
    return *(uint32_t*)&t;
}
__device__ __forceinline__ void splitpair(float v0, float v1,
                                          uint32_t& hi, uint32_t& lo) {
    float h0 = __bfloat162float(__float2bfloat16_rn(v0));
    float h1 = __bfloat162float(__float2bfloat16_rn(v1));
    hi = packbf(h0, h1);
    lo = packbf(v0 - h0, v1 - h1);
}

// ---------------- split-bf16 conversion -----------------------------------
__global__ void __launch_bounds__(256)
cvt_split(const float* __restrict__ in, __nv_bfloat16* __restrict__ hi,
          __nv_bfloat16* __restrict__ lo, int n4)
{
    int i = blockIdx.x * blockDim.x + threadIdx.x;
    if (i >= n4) return;
    float4 v = ((const float4*)in)[i];
    uint32_t h01, l01, h23, l23;
    splitpair(v.x, v.y, h01, l01);
    splitpair(v.z, v.w, h23, l23);
    ((uint2*)hi)[i] = make_uint2(h01, h23);
    ((uint2*)lo)[i] = make_uint2(l01, l23);
}

// ---------------- HMMA GEMM ------------------------------------------------
// C[m][n] = sum_k A[m][k]*W[n][k] (+bias), via 3-term split-bf16.
// Block 128x128, 8 warps as 4(m) x 2(n); warp tile 32x64. K-tile 32.
// Static smem: 4 tensors x 128 x 40 halves = 40960 bytes.
// LAYOUT 0: split result into (dstH, dstL) bf16 at [b,h,s,d], pre-scaled.
// LAYOUT 1: dstF[m*768+n] = beta*(acc+bias) + alpha*AO[m*768+n]
#define GPAD 40

template<int LAYOUT>
__global__ void __launch_bounds__(256)
gemm_mma(const __nv_bfloat16* __restrict__ Ah, const __nv_bfloat16* __restrict__ Al,
         const __nv_bfloat16* __restrict__ Wh, const __nv_bfloat16* __restrict__ Wl,
         const float* __restrict__ bias, float scale,
         __nv_bfloat16* __restrict__ dstH, __nv_bfloat16* __restrict__ dstL,
         float* __restrict__ dstF,
         const float* __restrict__ alphaP, const float* __restrict__ betaP,
         const float* __restrict__ add)
{
    __shared__ __nv_bfloat16 sm[4][128][GPAD];   // 0=Ah 1=Al 2=Wh 3=Wl
    const uint32_t sb = smem_u32(&sm[0][0][0]);
    const int tid  = threadIdx.x;
    const int lane = tid & 31;
    const int w    = tid >> 5;
    const int wm   = w & 3;          // 0..3 (m)
    const int wn   = w >> 2;         // 0..1 (n)
    const int m0 = blockIdx.x * 128;
    const int n0 = blockIdx.y * 128;

    float acc[2][8][4];
#pragma unroll
    for (int i = 0; i < 2; i++)
#pragma unroll
        for (int j = 0; j < 8; j++)
#pragma unroll
            for (int c = 0; c < 4; c++) acc[i][j][c] = 0.f;

    for (int k0 = 0; k0 < EMB; k0 += 32) {
        // 4 tensors x 128 rows x 32 halves = 2048 uint4; 8 per thread
#pragma unroll
        for (int u = 0; u < 8; u++) {
            int idx  = tid + u * 256;
            int tile = idx >> 9;           // 0..3
            int r    = (idx >> 2) & 127;
            int c8   = idx & 3;
            const __nv_bfloat16* src =
                (tile == 0) ? Ah : (tile == 1) ? Al : (tile == 2) ? Wh : Wl;
            int gr = ((tile < 2) ? m0 : n0) + r;
            uint4 v = *(const uint4*)(src + (size_t)gr * EMB + k0 + c8 * 8);
            *(uint4*)&sm[tile][r][c8 * 8] = v;
        }
        __syncthreads();

#pragma unroll
        for (int t = 0; t < 2; t++) {
            uint32_t ah[2][4], al_[2][4];
#pragma unroll
            for (int i = 0; i < 2; i++) {
                int row  = wm * 32 + i * 16 + (lane & 15);
                int colh = t * 16 + ((lane >> 4) << 3);
                ldm_x4(ah[i],  sb + (uint32_t)(0 * 128 * GPAD + row * GPAD + colh) * 2);
                ldm_x4(al_[i], sb + (uint32_t)(1 * 128 * GPAD + row * GPAD + colh) * 2);
            }
#pragma unroll
            for (int j = 0; j < 8; j++) {
                int row  = wn * 64 + j * 8 + (lane & 7);
                int colh = t * 16 + ((lane >> 3) & 1) * 8;
                uint32_t bh_[2], bl_[2];
                ldm_x2(bh_, sb + (uint32_t)(2 * 128 * GPAD + row * GPAD + colh) * 2);
                ldm_x2(bl_, sb + (uint32_t)(3 * 128 * GPAD + row * GPAD + colh) * 2);
#pragma unroll
                for (int i = 0; i < 2; i++) {
                    mma16816(acc[i][j], ah[i],  bh_[0], bh_[1]);
                    mma16816(acc[i][j], ah[i],  bl_[0], bl_[1]);
                    mma16816(acc[i][j], al_[i], bh_[0], bh_[1]);
                }
            }
        }
        __syncthreads();
    }

    // epilogue
    const int gid = lane >> 2, tig = lane & 3;
    const float al = LAYOUT ? *alphaP : 0.f;
    const float be = LAYOUT ? *betaP : 0.f;
#pragma unroll
    for (int i = 0; i < 2; i++) {
#pragma unroll
        for (int j = 0; j < 8; j++) {
            int row = m0 + wm * 32 + i * 16 + gid;
            int col = n0 + wn * 64 + j * 8 + tig * 2;
            float b0 = bias[col], b1 = bias[col + 1];
#pragma unroll
            for (int hrow = 0; hrow < 2; hrow++) {
                int m = row + hrow * 8;
                float v0 = acc[i][j][hrow * 2 + 0] + b0;
                float v1 = acc[i][j][hrow * 2 + 1] + b1;
                if (LAYOUT == 0) {
                    v0 *= scale; v1 *= scale;
                    uint32_t hi, lo;
                    splitpair(v0, v1, hi, lo);
                    int bi = m >> 11, si = m & 2047;
                    int h = col >> 6, d = col & 63;
                    size_t base = (((size_t)(bi * HEADS + h)) * SEQ + si) * DIM + d;
                    *(uint32_t*)&dstH[base] = hi;
                    *(uint32_t*)&dstL[base] = lo;
                } else {
                    size_t r = (size_t)m * EMB + col;
                    float2 ad = *(const float2*)&add[r];
                    float2 o;
                    o.x = be * v0 + al * ad.x;
                    o.y = be * v1 + al * ad.y;
                    *(float2*)&dstF[r] = o;
                }
            }
        }
    }
}

// ---------------- HMMA flash attention -------------------------------------
// Block: 128 q-rows x one (b,h). 8 warps x 16 q-rows. KV tiles 64.
// Q fragments loaded directly from gmem (no Q smem).
// Static smem: 4 tensors (KH,KL,VH,VL) x 64 x 72 halves = 36864 bytes.
#define APAD 72

__global__ void __launch_bounds__(256) attn_mma()
{
    __shared__ __nv_bfloat16 kvs[4][64][APAD];   // 0=KH 1=KL 2=VH 3=VL
    const uint32_t sb = smem_u32(&kvs[0][0][0]);
    const int tid  = threadIdx.x;
    const int lane = tid & 31;
    const int w    = tid >> 5;
    const int gid  = lane >> 2, tig = lane & 3;
    const int bh = blockIdx.y;
    const int q0 = blockIdx.x * 128;

    const size_t bhoff = (size_t)bh * SEQ * DIM;

    // Q fragments straight from gmem: a0={r,k2t}, a1={r+8,k2t}, a2={r,k2t+8}, a3={r+8,k2t+8}
    uint32_t qfh[4][4], qfl[4][4];
    {
        const int r0 = q0 + w * 16 + gid;
#pragma unroll
        for (int t = 0; t < 4; t++) {
            int kc = t * 16 + tig * 2;
            const __nv_bfloat16* ph_ = g_Qh + bhoff;
            const __nv_bfloat16* pl_ = g_Ql + bhoff;
            qfh[t][0] = *(const uint32_t*)(ph_ + (size_t)r0 * DIM + kc);
            qfh[t][1] = *(const uint32_t*)(ph_ + (size_t)(r0 + 8) * DIM + kc);
            qfh[t][2] = *(const uint32_t*)(ph_ + (size_t)r0 * DIM + kc + 8);
            qfh[t][3] = *(const uint32_t*)(ph_ + (size_t)(r0 + 8) * DIM + kc + 8);
            qfl[t][0] = *(const uint32_t*)(pl_ + (size_t)r0 * DIM + kc);
            qfl[t][1] = *(const uint32_t*)(pl_ + (size_t)(r0 + 8) * DIM + kc);
            qfl[t][2] = *(const uint32_t*)(pl_ + (size_t)r0 * DIM + kc + 8);
            qfl[t][3] = *(const uint32_t*)(pl_ + (size_t)(r0 + 8) * DIM + kc + 8);
        }
    }

    float m_[2] = {-1e30f, -1e30f};
    float l_[2] = {0.f, 0.f};
    float o[8][4];
#pragma unroll
    for (int j = 0; j < 8; j++)
#pragma unroll
        for (int c = 0; c < 4; c++) o[j][c] = 0.f;

    for (int kt = 0; kt < SEQ / 64; kt++) {
        const int kv0 = kt * 64;
        // load KH,KL,VH,VL: 4 x 64x64 halves = 2048 uint4; 8/thread
#pragma unroll
        for (int u = 0; u < 8; u++) {
            int idx = tid + u * 256;
            int tile = idx >> 9;           // 0..3
            int r = (idx >> 3) & 63;
            int c8 = idx & 7;
            const __nv_bfloat16* src =
                (tile == 0) ? g_Kh : (tile == 1) ? g_Kl : (tile == 2) ? g_Vh : g_Vl;
            uint4 v = *(const uint4*)(src + bhoff + (size_t)(kv0 + r) * DIM + c8 * 8);
            *(uint4*)&kvs[tile][r][c8 * 8] = v;
        }
        __syncthreads();

        // scores S[16 x 64] per warp
        float s[8][4];
#pragma unroll
        for (int j = 0; j < 8; j++)
#pragma unroll
            for (int c = 0; c < 4; c++) s[j][c] = 0.f;
#pragma unroll
        for (int j = 0; j < 8; j++) {
#pragma unroll
            for (int t = 0; t < 4; t++) {
                int row  = j * 8 + (lane & 7);
                int colh = t * 16 + ((lane >> 3) & 1) * 8;
                uint32_t bh_[2], bl_[2];
                ldm_x2(bh_, sb + (uint32_t)(0 * 64 * APAD + row * APAD + colh) * 2);
                ldm_x2(bl_, sb + (uint32_t)(1 * 64 * APAD + row * APAD + colh) * 2);
                mma16816(s[j], qfh[t], bh_[0], bh_[1]);
                mma16816(s[j], qfh[t], bl_[0], bl_[1]);
                mma16816(s[j], qfl[t], bh_[0], bh_[1]);
            }
        }

        // online softmax (rows gid, gid+8)
        float rmax[2] = {-1e30f, -1e30f};
#pragma unroll
        for (int j = 0; j < 8; j++) {
            rmax[0] = fmaxf(rmax[0], fmaxf(s[j][0], s[j][1]));
            rmax[1] = fmaxf(rmax[1], fmaxf(s[j][2], s[j][3]));
        }
#pragma unroll
        for (int d = 1; d < 4; d <<= 1) {
            rmax[0] = fmaxf(rmax[0], __shfl_xor_sync(0xffffffffu, rmax[0], d));
            rmax[1] = fmaxf(rmax[1], __shfl_xor_sync(0xffffffffu, rmax[1], d));
        }
        float mnew[2], corr[2];
        mnew[0] = fmaxf(m_[0], rmax[0]);
        mnew[1] = fmaxf(m_[1], rmax[1]);
        corr[0] = __expf(m_[0] - mnew[0]);
        corr[1] = __expf(m_[1] - mnew[1]);
        float rsum[2] = {0.f, 0.f};
#pragma unroll
        for (int j = 0; j < 8; j++) {
            s[j][0] = __expf(s[j][0] - mnew[0]);
            s[j][1] = __expf(s[j][1] - mnew[0]);
            s[j][2] = __expf(s[j][2] - mnew[1]);
            s[j][3] = __expf(s[j][3] - mnew[1]);
            rsum[0] += s[j][0] + s[j][1];
            rsum[1] += s[j][2] + s[j][3];
            o[j][0] *= corr[0]; o[j][1] *= corr[0];
            o[j][2] *= corr[1]; o[j][3] *= corr[1];
        }
#pragma unroll
        for (int d = 1; d < 4; d <<= 1) {
            rsum[0] += __shfl_xor_sync(0xffffffffu, rsum[0], d);
            rsum[1] += __shfl_xor_sync(0xffffffffu, rsum[1], d);
        }
        l_[0] = l_[0] * corr[0] + rsum[0];
        l_[1] = l_[1] * corr[1] + rsum[1];
        m_[0] = mnew[0]; m_[1] = mnew[1];

        // P·V: A-fragment k-tile t from C n-tiles 2t, 2t+1
#pragma unroll
        for (int t = 0; t < 4; t++) {
            uint32_t ph[4], pl[4];
            splitpair(s[2*t][0],   s[2*t][1],   ph[0], pl[0]);
            splitpair(s[2*t][2],   s[2*t][3],   ph[1], pl[1]);
            splitpair(s[2*t+1][0], s[2*t+1][1], ph[2], pl[2]);
            splitpair(s[2*t+1][2], s[2*t+1][3], ph[3], pl[3]);
#pragma unroll
            for (int j = 0; j < 8; j++) {
                int row = t * 16 + (lane & 7) + ((lane >> 3) & 1) * 8;
                uint32_t bvh[2], bvl[2];
                ldm_x2t(bvh, sb + (uint32_t)(2 * 64 * APAD + row * APAD + j * 8) * 2);
                ldm_x2t(bvl, sb + (uint32_t)(3 * 64 * APAD + row * APAD + j * 8) * 2);
                mma16816(o[j], ph, bvh[0], bvh[1]);
                mma16816(o[j], ph, bvl[0], bvl[1]);
                mma16816(o[j], pl, bvh[0], bvh[1]);
            }
        }
        __syncthreads();
    }

    // epilogue -> g_AO [b, s, h*64+d] fp32
    const int bi = bh / HEADS;
    const int h  = bh % HEADS;
    float inv0 = 1.f / l_[0];
    float inv1 = 1.f / l_[1];
#pragma unroll
    for (int j = 0; j < 8; j++) {
        int q = q0 + w * 16 + gid;
        int d = j * 8 + tig * 2;
        float2 v0 = make_float2(o[j][0] * inv0, o[j][1] * inv0);
        float2 v1 = make_float2(o[j][2] * inv1, o[j][3] * inv1);
        *(float2*)&g_AO[((size_t)(bi * SEQ + q)) * EMB + h * DIM + d] = v0;
        *(float2*)&g_AO[((size_t)(bi * SEQ + q + 8)) * EMB + h * DIM + d] = v1;
    }
}

// ---------------------------------------------------------------------------
extern "C" void kernel_launch(void* const* d_in, const int* in_sizes, int n_in,
                              void* d_out, int out_size)
{
    const float* v1    = (const float*)d_in[0];
    const float* v2    = (const float*)d_in[1];
    const float* Wq    = (const float*)d_in[2];
    const float* bq    = (const float*)d_in[3];
    const float* Wk    = (const float*)d_in[4];
    const float* bk    = (const float*)d_in[5];
    const float* Wv    = (const float*)d_in[6];
    const float* bv    = (const float*)d_in[7];
    const float* Wo    = (const float*)d_in[8];
    const float* bo    = (const float*)d_in[9];
    const float* alpha = (const float*)d_in[10];
    const float* beta  = (const float*)d_in[11];
    float* out = (float*)d_out;

    float *AOp;
    __nv_bfloat16 *v1h, *v1l, *v2h, *v2l, *Wh, *Wl;
    __nv_bfloat16 *Qh, *Ql, *Kh, *Kl, *Vh, *Vl;
    cudaGetSymbolAddress((void**)&AOp, g_AO);
    cudaGetSymbolAddress((void**)&v1h, g_v1h);
    cudaGetSymbolAddress((void**)&v1l, g_v1l);
    cudaGetSymbolAddress((void**)&v2h, g_v2h);
    cudaGetSymbolAddress((void**)&v2l, g_v2l);
    cudaGetSymbolAddress((void**)&Wh,  g_Wh);
    cudaGetSymbolAddress((void**)&Wl,  g_Wl);
    cudaGetSymbolAddress((void**)&Qh,  g_Qh);
    cudaGetSymbolAddress((void**)&Ql,  g_Ql);
    cudaGetSymbolAddress((void**)&Kh,  g_Kh);
    cudaGetSymbolAddress((void**)&Kl,  g_Kl);
    cudaGetSymbolAddress((void**)&Vh,  g_Vh);
    cudaGetSymbolAddress((void**)&Vl,  g_Vl);

    const int nAct4 = MROWS * EMB / 4;
    const int nW4   = EMB * EMB / 4;
    cvt_split<<<(nAct4 + 255) / 256, 256>>>(v1, v1h, v1l, nAct4);
    cvt_split<<<(nAct4 + 255) / 256, 256>>>(v2, v2h, v2l, nAct4);
    cvt_split<<<(nW4 + 255) / 256, 256>>>(Wq, Wh + 0 * EMB * EMB, Wl + 0 * EMB * EMB, nW4);
    cvt_split<<<(nW4 + 255) / 256, 256>>>(Wk, Wh + 1 * EMB * EMB, Wl + 1 * EMB * EMB, nW4);
    cvt_split<<<(nW4 + 255) / 256, 256>>>(Wv, Wh + 2 * EMB * EMB, Wl + 2 * EMB * EMB, nW4);
    cvt_split<<<(nW4 + 255) / 256, 256>>>(Wo, Wh + 3 * EMB * EMB, Wl + 3 * EMB * EMB, nW4);

    const float qscale = 1.0f / sqrtf((float)EMB);
    dim3 gg(MROWS / 128, EMB / 128);

    gemm_mma<0><<<gg, 256>>>(v1h, v1l, Wh + 0 * EMB * EMB, Wl + 0 * EMB * EMB,
                             bq, qscale, Qh, Ql, nullptr, nullptr, nullptr, nullptr);
    gemm_mma<0><<<gg, 256>>>(v2h, v2l, Wh + 1 * EMB * EMB, Wl + 1 * EMB * EMB,
                             bk, 1.0f, Kh, Kl, nullptr, nullptr, nullptr, nullptr);
    gemm_mma<0><<<gg, 256>>>(v2h, v2l, Wh + 2 * EMB * EMB, Wl + 2 * EMB * EMB,
                             bv, 1.0f, Vh, Vl, nullptr, nullptr, nullptr, nullptr);

    attn_mma<<<dim3(SEQ / 128, BATCH * HEADS), 256>>>();

    gemm_mma<1><<<gg, 256>>>(v1h, v1l, Wh + 3 * EMB * EMB, Wl + 3 * EMB * EMB,
                             bo, 1.0f, nullptr, nullptr, out, alpha, beta, AOp);
}

// round 6
// speedup vs baseline: 2.9087x; 1.0615x over previous
#include <cuda_runtime.h>
#include <cuda_bf16.h>
#include <math.h>
#include <stdint.h>

#define HEADS 12
#define SEQ   2048
#define DIM   64
#define EMB   768
#define BATCH 4
#define MROWS (BATCH*SEQ)   // 8192

// ---------------- scratch (static device globals; no allocation) ----------
__device__ float g_AO[MROWS*EMB];            // attention out, [B*S, 768]

__device__ __nv_bfloat16 g_Qh[BATCH*HEADS*SEQ*DIM];
__device__ __nv_bfloat16 g_Ql[BATCH*HEADS*SEQ*DIM];
__device__ __nv_bfloat16 g_Kh[BATCH*HEADS*SEQ*DIM];
__device__ __nv_bfloat16 g_Kl[BATCH*HEADS*SEQ*DIM];
__device__ __nv_bfloat16 g_Vh[BATCH*HEADS*SEQ*DIM];
__device__ __nv_bfloat16 g_Vl[BATCH*HEADS*SEQ*DIM];

__device__ __nv_bfloat16 g_v1h[MROWS*EMB];
__device__ __nv_bfloat16 g_v1l[MROWS*EMB];
__device__ __nv_bfloat16 g_v2h[MROWS*EMB];
__device__ __nv_bfloat16 g_v2l[MROWS*EMB];
__device__ __nv_bfloat16 g_Wh[4*EMB*EMB];    // slots: 0=q 1=k 2=v 3=o
__device__ __nv_bfloat16 g_Wl[4*EMB*EMB];

// ---------------- helpers --------------------------------------------------
__device__ __forceinline__ uint32_t smem_u32(const void* p) {
    uint32_t a;
    asm("{ .reg .u64 t; cvta.to.shared.u64 t, %1; cvt.u32.u64 %0, t; }"
        : "=r"(a) : "l"(p));
    return a;
}
__device__ __forceinline__ void mma16816(float* c, const uint32_t* a,
                                         uint32_t b0, uint32_t b1) {
    asm volatile(
        "mma.sync.aligned.m16n8k16.row.col.f32.bf16.bf16.f32 "
        "{%0,%1,%2,%3}, {%4,%5,%6,%7}, {%8,%9}, {%0,%1,%2,%3};"
        : "+f"(c[0]), "+f"(c[1]), "+f"(c[2]), "+f"(c[3])
        : "r"(a[0]), "r"(a[1]), "r"(a[2]), "r"(a[3]), "r"(b0), "r"(b1));
}
__device__ __forceinline__ void ldm_x4(uint32_t* r, uint32_t addr) {
    asm volatile("ldmatrix.sync.aligned.m8n8.x4.shared.b16 {%0,%1,%2,%3}, [%4];"
                 : "=r"(r[0]), "=r"(r[1]), "=r"(r[2]), "=r"(r[3]) : "r"(addr));
}
__device__ __forceinline__ void ldm_x4t(uint32_t* r, uint32_t addr) {
    asm volatile("ldmatrix.sync.aligned.m8n8.x4.trans.shared.b16 {%0,%1,%2,%3}, [%4];"
                 : "=r"(r[0]), "=r"(r[1]), "=r"(r[2]), "=r"(r[3]) : "r"(addr));
}
#define CP_A16(dst, src) \
    asm volatile("cp.async.cg.shared.global [%0], [%1], 16;" :: "r"(dst), "l"(src))
#define CP_COMMIT() asm volatile("cp.async.commit_group;" ::: "memory")
#define CP_WAIT1()  asm volatile("cp.async.wait_group 1;" ::: "memory")
#define CP_WAIT0()  asm volatile("cp.async.wait_group 0;" ::: "memory")

__device__ __forceinline__ uint32_t packbf(float lo, float hi) {
    __nv_bfloat162 t = __floats2bfloat162_rn(lo, hi);
    return *(uint32_t*)&t;
}
__device__ __forceinline__ void splitpair(float v0, float v1,
                                          uint32_t& hi, uint32_t& lo) {
    float h0 = __bfloat162float(__float2bfloat16_rn(v0));
    float h1 = __bfloat162float(__float2bfloat16_rn(v1));
    hi = packbf(h0, h1);
    lo = packbf(v0 - h0, v1 - h1);
}

// ---------------- split-bf16 conversion -----------------------------------
__global__ void __launch_bounds__(256)
cvt_split(const float* __restrict__ in, __nv_bfloat16* __restrict__ hi,
          __nv_bfloat16* __restrict__ lo, int n4)
{
    int i = blockIdx.x * blockDim.x + threadIdx.x;
    if (i >= n4) return;
    float4 v = ((const float4*)in)[i];
    uint32_t h01, l01, h23, l23;
    splitpair(v.x, v.y, h01, l01);
    splitpair(v.z, v.w, h23, l23);
    ((uint2*)hi)[i] = make_uint2(h01, h23);
    ((uint2*)lo)[i] = make_uint2(l01, l23);
}
// 4 weights in one launch (blockIdx.y = slot)
__global__ void __launch_bounds__(256)
cvt_split_w(const float* __restrict__ w0, const float* __restrict__ w1,
            const float* __restrict__ w2, const float* __restrict__ w3,
            __nv_bfloat16* __restrict__ hi, __nv_bfloat16* __restrict__ lo, int n4)
{
    int i = blockIdx.x * blockDim.x + threadIdx.x;
    if (i >= n4) return;
    int s = blockIdx.y;
    const float* in = (s == 0) ? w0 : (s == 1) ? w1 : (s == 2) ? w2 : w3;
    float4 v = ((const float4*)in)[i];
    uint32_t h01, l01, h23, l23;
    splitpair(v.x, v.y, h01, l01);
    splitpair(v.z, v.w, h23, l23);
    size_t off = (size_t)s * (EMB * EMB / 4) + i;
    ((uint2*)hi)[off] = make_uint2(h01, h23);
    ((uint2*)lo)[off] = make_uint2(l01, l23);
}

// ---------------- HMMA GEMM (cp.async 2-stage, K-tile 16) ------------------
// Block 128x128, 8 warps as 4(m) x 2(n); warp tile 32x64.
// smem: 2 stages x 4 tensors x 128 x 24 halves = 49152 B (48KB exactly).
#define GKT  16
#define GPAD 24
#define GTEN (128*GPAD)          // halves per tensor
#define GSTG (4*GTEN)            // halves per stage

template<int LAYOUT>
__global__ void __launch_bounds__(256)
gemm_mma(const __nv_bfloat16* __restrict__ Ah, const __nv_bfloat16* __restrict__ Al,
         const __nv_bfloat16* __restrict__ Wh, const __nv_bfloat16* __restrict__ Wl,
         const float* __restrict__ bias, float scale,
         __nv_bfloat16* __restrict__ dstH, __nv_bfloat16* __restrict__ dstL,
         float* __restrict__ dstF,
         const float* __restrict__ alphaP, const float* __restrict__ betaP,
         const float* __restrict__ add)
{
    __shared__ __nv_bfloat16 sm[2][4][128][GPAD];
    const uint32_t sb = smem_u32(&sm[0][0][0][0]);
    const int tid  = threadIdx.x;
    const int lane = tid & 31;
    const int w    = tid >> 5;
    const int wm   = w & 3;
    const int wn   = w >> 2;
    const int m0 = blockIdx.x * 128;
    const int n0 = blockIdx.y * 128;

    const __nv_bfloat16* srcs[4] = {Ah, Al, Wh, Wl};
    const int rb[4] = {m0, m0, n0, n0};

    // prefetch lambda-ish macro
    auto prefetch = [&](int kt, int st) {
#pragma unroll
        for (int u = 0; u < 4; u++) {
            int idx  = tid + u * 256;
            int tile = idx >> 8;
            int r    = (idx >> 1) & 127;
            int c    = idx & 1;
            uint32_t dst = sb + (uint32_t)(st * GSTG + tile * GTEN + r * GPAD + c * 8) * 2;
            CP_A16(dst, srcs[tile] + (size_t)(rb[tile] + r) * EMB + kt * GKT + c * 8);
        }
        CP_COMMIT();
    };

    float acc[2][8][4];
#pragma unroll
    for (int i = 0; i < 2; i++)
#pragma unroll
        for (int j = 0; j < 8; j++)
#pragma unroll
            for (int c = 0; c < 4; c++) acc[i][j][c] = 0.f;

    prefetch(0, 0);
    const int NKT = EMB / GKT;   // 48
    for (int kt = 0; kt < NKT; kt++) {
        const int st = kt & 1;
        if (kt + 1 < NKT) { prefetch(kt + 1, st ^ 1); CP_WAIT1(); }
        else              { CP_WAIT0(); }
        __syncthreads();

        const uint32_t so = sb + (uint32_t)(st * GSTG) * 2;
        uint32_t ah[2][4], al_[2][4];
#pragma unroll
        for (int i = 0; i < 2; i++) {
            int row  = wm * 32 + i * 16 + (lane & 15);
            int colh = (lane >> 4) << 3;
            ldm_x4(ah[i],  so + (uint32_t)(0 * GTEN + row * GPAD + colh) * 2);
            ldm_x4(al_[i], so + (uint32_t)(1 * GTEN + row * GPAD + colh) * 2);
        }
#pragma unroll
        for (int jp = 0; jp < 4; jp++) {
            int row  = wn * 64 + jp * 16 + ((lane >> 4) << 3) + (lane & 7);
            int colh = ((lane >> 3) & 1) << 3;
            uint32_t bh4[4], bl4[4];
            ldm_x4(bh4, so + (uint32_t)(2 * GTEN + row * GPAD + colh) * 2);
            ldm_x4(bl4, so + (uint32_t)(3 * GTEN + row * GPAD + colh) * 2);
#pragma unroll
            for (int i = 0; i < 2; i++) {
                mma16816(acc[i][2*jp],   ah[i],  bh4[0], bh4[1]);
                mma16816(acc[i][2*jp],   ah[i],  bl4[0], bl4[1]);
                mma16816(acc[i][2*jp],   al_[i], bh4[0], bh4[1]);
                mma16816(acc[i][2*jp+1], ah[i],  bh4[2], bh4[3]);
                mma16816(acc[i][2*jp+1], ah[i],  bl4[2], bl4[3]);
                mma16816(acc[i][2*jp+1], al_[i], bh4[2], bh4[3]);
            }
        }
        __syncthreads();
    }

    // epilogue
    const int gid = lane >> 2, tig = lane & 3;
    const float al = LAYOUT ? *alphaP : 0.f;
    const float be = LAYOUT ? *betaP : 0.f;
#pragma unroll
    for (int i = 0; i < 2; i++) {
#pragma unroll
        for (int j = 0; j < 8; j++) {
            int row = m0 + wm * 32 + i * 16 + gid;
            int col = n0 + wn * 64 + j * 8 + tig * 2;
            float b0 = bias[col], b1 = bias[col + 1];
#pragma unroll
            for (int hrow = 0; hrow < 2; hrow++) {
                int m = row + hrow * 8;
                float v0 = acc[i][j][hrow * 2 + 0] + b0;
                float v1 = acc[i][j][hrow * 2 + 1] + b1;
                if (LAYOUT == 0) {
                    v0 *= scale; v1 *= scale;
                    uint32_t hi, lo;
                    splitpair(v0, v1, hi, lo);
                    int bi = m >> 11, si = m & 2047;
                    int h = col >> 6, d = col & 63;
                    size_t base = (((size_t)(bi * HEADS + h)) * SEQ + si) * DIM + d;
                    *(uint32_t*)&dstH[base] = hi;
                    *(uint32_t*)&dstL[base] = lo;
                } else {
                    size_t r = (size_t)m * EMB + col;
                    float2 ad = *(const float2*)&add[r];
                    float2 o;
                    o.x = be * v0 + al * ad.x;
                    o.y = be * v1 + al * ad.y;
                    *(float2*)&dstF[r] = o;
                }
            }
        }
    }
}

// ---------------- HMMA flash attention (cp.async 2-stage, KV tile 32) ------
// Block: 128 q-rows x one (b,h). 8 warps x 16 q-rows.
// smem: 2 stages x 4 tensors (KH,KL,VH,VL) x 32 x 72 halves = 36864 B.
#define KVT  32
#define APAD 72
#define ATEN (KVT*APAD)
#define ASTG (4*ATEN)

__global__ void __launch_bounds__(256) attn_mma()
{
    __shared__ __nv_bfloat16 kvs[2][4][KVT][APAD];
    const uint32_t sb = smem_u32(&kvs[0][0][0][0]);
    const int tid  = threadIdx.x;
    const int lane = tid & 31;
    const int w    = tid >> 5;
    const int gid  = lane >> 2, tig = lane & 3;
    const int bh = blockIdx.y;
    const int q0 = blockIdx.x * 128;

    const size_t bhoff = (size_t)bh * SEQ * DIM;
    const __nv_bfloat16* srcs[4] = {g_Kh + bhoff, g_Kl + bhoff, g_Vh + bhoff, g_Vl + bhoff};

    auto prefetch = [&](int kt, int st) {
#pragma unroll
        for (int u = 0; u < 4; u++) {
            int idx  = tid + u * 256;
            int tile = idx >> 8;
            int r    = (idx >> 3) & 31;
            int c8   = idx & 7;
            uint32_t dst = sb + (uint32_t)(st * ASTG + tile * ATEN + r * APAD + c8 * 8) * 2;
            CP_A16(dst, srcs[tile] + (size_t)(kt * KVT + r) * DIM + c8 * 8);
        }
        CP_COMMIT();
    };

    // Q fragments straight from gmem
    uint32_t qfh[4][4], qfl[4][4];
    {
        const int r0 = q0 + w * 16 + gid;
#pragma unroll
        for (int t = 0; t < 4; t++) {
            int kc = t * 16 + tig * 2;
            const __nv_bfloat16* ph_ = g_Qh + bhoff;
            const __nv_bfloat16* pl_ = g_Ql + bhoff;
            qfh[t][0] = *(const uint32_t*)(ph_ + (size_t)r0 * DIM + kc);
            qfh[t][1] = *(const uint32_t*)(ph_ + (size_t)(r0 + 8) * DIM + kc);
            qfh[t][2] = *(const uint32_t*)(ph_ + (size_t)r0 * DIM + kc + 8);
            qfh[t][3] = *(const uint32_t*)(ph_ + (size_t)(r0 + 8) * DIM + kc + 8);
            qfl[t][0] = *(const uint32_t*)(pl_ + (size_t)r0 * DIM + kc);
            qfl[t][1] = *(const uint32_t*)(pl_ + (size_t)(r0 + 8) * DIM + kc);
            qfl[t][2] = *(const uint32_t*)(pl_ + (size_t)r0 * DIM + kc + 8);
            qfl[t][3] = *(const uint32_t*)(pl_ + (size_t)(r0 + 8) * DIM + kc + 8);
        }
    }

    float m_[2] = {-1e30f, -1e30f};
    float l_[2] = {0.f, 0.f};
    float o[8][4];
#pragma unroll
    for (int j = 0; j < 8; j++)
#pragma unroll
        for (int c = 0; c < 4; c++) o[j][c] = 0.f;

    prefetch(0, 0);
    const int NT = SEQ / KVT;    // 64
    for (int kt = 0; kt < NT; kt++) {
        const int st = kt & 1;
        if (kt + 1 < NT) { prefetch(kt + 1, st ^ 1); CP_WAIT1(); }
        else             { CP_WAIT0(); }
        __syncthreads();
        const uint32_t so = sb + (uint32_t)(st * ASTG) * 2;

        // scores S[16 x 32] per warp
        float s[4][4];
#pragma unroll
        for (int j = 0; j < 4; j++)
#pragma unroll
            for (int c = 0; c < 4; c++) s[j][c] = 0.f;
#pragma unroll
        for (int jp = 0; jp < 2; jp++) {
#pragma unroll
            for (int t = 0; t < 4; t++) {
                int row  = jp * 16 + ((lane >> 4) << 3) + (lane & 7);
                int colh = t * 16 + (((lane >> 3) & 1) << 3);
                uint32_t kh4[4], kl4[4];
                ldm_x4(kh4, so + (uint32_t)(0 * ATEN + row * APAD + colh) * 2);
                ldm_x4(kl4, so + (uint32_t)(1 * ATEN + row * APAD + colh) * 2);
                mma16816(s[2*jp],   qfh[t], kh4[0], kh4[1]);
                mma16816(s[2*jp],   qfh[t], kl4[0], kl4[1]);
                mma16816(s[2*jp],   qfl[t], kh4[0], kh4[1]);
                mma16816(s[2*jp+1], qfh[t], kh4[2], kh4[3]);
                mma16816(s[2*jp+1], qfh[t], kl4[2], kl4[3]);
                mma16816(s[2*jp+1], qfl[t], kh4[2], kh4[3]);
            }
        }

        // online softmax (rows gid, gid+8)
        float rmax[2] = {-1e30f, -1e30f};
#pragma unroll
        for (int j = 0; j < 4; j++) {
            rmax[0] = fmaxf(rmax[0], fmaxf(s[j][0], s[j][1]));
            rmax[1] = fmaxf(rmax[1], fmaxf(s[j][2], s[j][3]));
        }
#pragma unroll
        for (int d = 1; d < 4; d <<= 1) {
            rmax[0] = fmaxf(rmax[0], __shfl_xor_sync(0xffffffffu, rmax[0], d));
            rmax[1] = fmaxf(rmax[1], __shfl_xor_sync(0xffffffffu, rmax[1], d));
        }
        float mnew[2], corr[2];
        mnew[0] = fmaxf(m_[0], rmax[0]);
        mnew[1] = fmaxf(m_[1], rmax[1]);
        corr[0] = __expf(m_[0] - mnew[0]);
        corr[1] = __expf(m_[1] - mnew[1]);
        float rsum[2] = {0.f, 0.f};
#pragma unroll
        for (int j = 0; j < 4; j++) {
            s[j][0] = __expf(s[j][0] - mnew[0]);
            s[j][1] = __expf(s[j][1] - mnew[0]);
            s[j][2] = __expf(s[j][2] - mnew[1]);
            s[j][3] = __expf(s[j][3] - mnew[1]);
            rsum[0] += s[j][0] + s[j][1];
            rsum[1] += s[j][2] + s[j][3];
        }
#pragma unroll
        for (int j = 0; j < 8; j++) {
            o[j][0] *= corr[0]; o[j][1] *= corr[0];
            o[j][2] *= corr[1]; o[j][3] *= corr[1];
        }
#pragma unroll
        for (int d = 1; d < 4; d <<= 1) {
            rsum[0] += __shfl_xor_sync(0xffffffffu, rsum[0], d);
            rsum[1] += __shfl_xor_sync(0xffffffffu, rsum[1], d);
        }
        l_[0] = l_[0] * corr[0] + rsum[0];
        l_[1] = l_[1] * corr[1] + rsum[1];
        m_[0] = mnew[0]; m_[1] = mnew[1];

        // P·V: A-fragment k-tile t from C n-tiles 2t, 2t+1
#pragma unroll
        for (int t = 0; t < 2; t++) {
            uint32_t ph[4], pl[4];
            splitpair(s[2*t][0],   s[2*t][1],   ph[0], pl[0]);
            splitpair(s[2*t][2],   s[2*t][3],   ph[1], pl[1]);
            splitpair(s[2*t+1][0], s[2*t+1][1], ph[2], pl[2]);
            splitpair(s[2*t+1][2], s[2*t+1][3], ph[3], pl[3]);
#pragma unroll
            for (int jp = 0; jp < 4; jp++) {
                int row = t * 16 + (((lane >> 3) & 1) << 3) + (lane & 7);
                int col = jp * 16 + ((lane >> 4) << 3);
                uint32_t vh4[4], vl4[4];
                ldm_x4t(vh4, so + (uint32_t)(2 * ATEN + row * APAD + col) * 2);
                ldm_x4t(vl4, so + (uint32_t)(3 * ATEN + row * APAD + col) * 2);
                mma16816(o[2*jp],   ph, vh4[0], vh4[1]);
                mma16816(o[2*jp],   ph, vl4[0], vl4[1]);
                mma16816(o[2*jp],   pl, vh4[0], vh4[1]);
                mma16816(o[2*jp+1], ph, vh4[2], vh4[3]);
                mma16816(o[2*jp+1], ph, vl4[2], vl4[3]);
                mma16816(o[2*jp+1], pl, vh4[2], vh4[3]);
            }
        }
        __syncthreads();
    }

    // epilogue -> g_AO [b, s, h*64+d] fp32
    const int bi = bh / HEADS;
    const int h  = bh % HEADS;
    float inv0 = 1.f / l_[0];
    float inv1 = 1.f / l_[1];
#pragma unroll
    for (int j = 0; j < 8; j++) {
        int q = q0 + w * 16 + gid;
        int d = j * 8 + tig * 2;
        float2 v0 = make_float2(o[j][0] * inv0, o[j][1] * inv0);
        float2 v1 = make_float2(o[j][2] * inv1, o[j][3] * inv1);
        *(float2*)&g_AO[((size_t)(bi * SEQ + q)) * EMB + h * DIM + d] = v0;
        *(float2*)&g_AO[((size_t)(bi * SEQ + q + 8)) * EMB + h * DIM + d] = v1;
    }
}

// ---------------------------------------------------------------------------
extern "C" void kernel_launch(void* const* d_in, const int* in_sizes, int n_in,
                              void* d_out, int out_size)
{
    const float* v1    = (const float*)d_in[0];
    const float* v2    = (const float*)d_in[1];
    const float* Wq    = (const float*)d_in[2];
    const float* bq    = (const float*)d_in[3];
    const float* Wk    = (const float*)d_in[4];
    const float* bk    = (const float*)d_in[5];
    const float* Wv    = (const float*)d_in[6];
    const float* bv    = (const float*)d_in[7];
    const float* Wo    = (const float*)d_in[8];
    const float* bo    = (const float*)d_in[9];
    const float* alpha = (const float*)d_in[10];
    const float* beta  = (const float*)d_in[11];
    float* out = (float*)d_out;

    float *AOp;
    __nv_bfloat16 *v1h, *v1l, *v2h, *v2l, *Wh, *Wl;
    __nv_bfloat16 *Qh, *Ql, *Kh, *Kl, *Vh, *Vl;
    cudaGetSymbolAddress((void**)&AOp, g_AO);
    cudaGetSymbolAddress((void**)&v1h, g_v1h);
    cudaGetSymbolAddress((void**)&v1l, g_v1l);
    cudaGetSymbolAddress((void**)&v2h, g_v2h);
    cudaGetSymbolAddress((void**)&v2l, g_v2l);
    cudaGetSymbolAddress((void**)&Wh,  g_Wh);
    cudaGetSymbolAddress((void**)&Wl,  g_Wl);
    cudaGetSymbolAddress((void**)&Qh,  g_Qh);
    cudaGetSymbolAddress((void**)&Ql,  g_Ql);
    cudaGetSymbolAddress((void**)&Kh,  g_Kh);
    cudaGetSymbolAddress((void**)&Kl,  g_Kl);
    cudaGetSymbolAddress((void**)&Vh,  g_Vh);
    cudaGetSymbolAddress((void**)&Vl,  g_Vl);

    const int nAct4 = MROWS * EMB / 4;
    const int nW4   = EMB * EMB / 4;
    cvt_split<<<(nAct4 + 255) / 256, 256>>>(v1, v1h, v1l, nAct4);
    cvt_split<<<(nAct4 + 255) / 256, 256>>>(v2, v2h, v2l, nAct4);
    cvt_split_w<<<dim3((nW4 + 255) / 256, 4), 256>>>(Wq, Wk, Wv, Wo, Wh, Wl, nW4);

    const float qscale = 1.0f / sqrtf((float)EMB);
    dim3 gg(MROWS / 128, EMB / 128);

    gemm_mma<0><<<gg, 256>>>(v1h, v1l, Wh + 0 * EMB * EMB, Wl + 0 * EMB * EMB,
                             bq, qscale, Qh, Ql, nullptr, nullptr, nullptr, nullptr);
    gemm_mma<0><<<gg, 256>>>(v2h, v2l, Wh + 1 * EMB * EMB, Wl + 1 * EMB * EMB,
                             bk, 1.0f, Kh, Kl, nullptr, nullptr, nullptr, nullptr);
    gemm_mma<0><<<gg, 256>>>(v2h, v2l, Wh + 2 * EMB * EMB, Wl + 2 * EMB * EMB,
                             bv, 1.0f, Vh, Vl, nullptr, nullptr, nullptr, nullptr);

    attn_mma<<<dim3(SEQ / 128, BATCH * HEADS), 256>>>();

    gemm_mma<1><<<gg, 256>>>(v1h, v1l, Wh + 3 * EMB * EMB, Wl + 3 * EMB * EMB,
                             bo, 1.0f, nullptr, nullptr, out, alpha, beta, AOp);
}